// round 3
// baseline (speedup 1.0000x reference)
#include <cuda_runtime.h>
#include <cstdint>

#define PI_F 3.14159265358979323846f
#define LOG2E_F 1.44269504088896340736f

constexpr int C_IN   = 256;
constexpr int HW     = 256 * 256;      // 65536
constexpr int BATCH  = 8;
constexpr int PPT    = 4;              // pixels per thread (float4)
constexpr int NTHR   = 128;
constexpr int PPB    = NTHR * PPT;     // 512 pixels per block

// ---- fast math helpers (MUFU-based) ----
__device__ __forceinline__ float ex2_(float x) {
    float y; asm("ex2.approx.f32 %0, %1;" : "=f"(y) : "f"(x)); return y;
}
__device__ __forceinline__ float rcp_(float x) {
    float y; asm("rcp.approx.f32 %0, %1;" : "=f"(y) : "f"(x)); return y;
}
__device__ __forceinline__ float rsq_(float x) {
    float y; asm("rsqrt.approx.f32 %0, %1;" : "=f"(y) : "f"(x)); return y;
}
__device__ __forceinline__ float sigmoid_(float x) {
    return rcp_(1.0f + ex2_(-LOG2E_F * x));
}
__device__ __forceinline__ float tanh_(float x) {
    return 1.0f - 2.0f * rcp_(1.0f + ex2_(2.0f * LOG2E_F * x));
}

// ---- packed f32x2 FMA (FFMA2, sm_103a; only reachable via PTX) ----
__device__ __forceinline__ void ffma2_(unsigned long long& d,
                                       unsigned long long a,
                                       unsigned long long b) {
    asm("fma.rn.f32x2 %0, %1, %2, %0;" : "+l"(d) : "l"(a), "l"(b));
}
__device__ __forceinline__ float2 unpack2_(unsigned long long v) {
    float2 r;
    asm("mov.b64 {%0, %1}, %2;" : "=f"(r.x), "=f"(r.y) : "l"(v));
    return r;
}

__global__ __launch_bounds__(NTHR, 8)
void brdf_fused_kernel(const float* __restrict__ feats,
                       const float* __restrict__ wi,
                       const float* __restrict__ wo,
                       const float* __restrict__ w_normal,
                       const float* __restrict__ w_albedo,
                       const float* __restrict__ w_rough,
                       const float* __restrict__ w_fresnel,
                       float* __restrict__ out_imgs,
                       float* __restrict__ out_data)
{
    // Weights pre-duplicated for f32x2: per channel 10 pairs (w,w) = 80 B
    // = 5 x LDS.128, each yielding two ready f32x2 broadcast operands.
    __shared__ float sw[C_IN * 20];

    const int tid = threadIdx.x;
    for (int i = tid; i < C_IN; i += NTHR) {
        float* p = &sw[i * 20];
        const float w0 = w_normal[0 * C_IN + i];
        const float w1 = w_normal[1 * C_IN + i];
        const float w2 = w_normal[2 * C_IN + i];
        const float w3 = w_albedo[0 * C_IN + i];
        const float w4 = w_albedo[1 * C_IN + i];
        const float w5 = w_albedo[2 * C_IN + i];
        const float w6 = w_rough[i];
        const float w7 = w_fresnel[0 * C_IN + i];
        const float w8 = w_fresnel[1 * C_IN + i];
        const float w9 = w_fresnel[2 * C_IN + i];
        p[0]  = w0; p[1]  = w0;
        p[2]  = w1; p[3]  = w1;
        p[4]  = w2; p[5]  = w2;
        p[6]  = w3; p[7]  = w3;
        p[8]  = w4; p[9]  = w4;
        p[10] = w5; p[11] = w5;
        p[12] = w6; p[13] = w6;
        p[14] = w7; p[15] = w7;
        p[16] = w8; p[17] = w8;
        p[18] = w9; p[19] = w9;
    }
    __syncthreads();

    const long long gpix = (long long)blockIdx.x * PPB + (long long)tid * PPT;
    const int b  = (int)(gpix / HW);
    const int hw = (int)(gpix % HW);

    // feats LDG.128 read as ulonglong2: .x = (px0,px1) f32x2, .y = (px2,px3).
    const ulonglong2* __restrict__ fp =
        reinterpret_cast<const ulonglong2*>(feats + (size_t)b * C_IN * HW + hw);
    const size_t cstride = HW / 4;   // 16-byte units per channel plane

    unsigned long long acc01[10], acc23[10];
#pragma unroll
    for (int o = 0; o < 10; ++o) { acc01[o] = 0ull; acc23[o] = 0ull; }

    const ulonglong2* __restrict__ swp =
        reinterpret_cast<const ulonglong2*>(sw);

#pragma unroll 4
    for (int c = 0; c < C_IN; ++c) {
        const ulonglong2 f = fp[0];
        fp += cstride;
        const ulonglong2 q0 = swp[0];
        const ulonglong2 q1 = swp[1];
        const ulonglong2 q2 = swp[2];
        const ulonglong2 q3 = swp[3];
        const ulonglong2 q4 = swp[4];
        swp += 5;
        const unsigned long long w2v[10] = {q0.x, q0.y, q1.x, q1.y, q2.x,
                                            q2.y, q3.x, q3.y, q4.x, q4.y};
#pragma unroll
        for (int o = 0; o < 10; ++o) {
            ffma2_(acc01[o], f.x, w2v[o]);
            ffma2_(acc23[o], f.y, w2v[o]);
        }
    }

    // Unpack accumulators: acc[o][j]
    float acc[10][4];
#pragma unroll
    for (int o = 0; o < 10; ++o) {
        const float2 a = unpack2_(acc01[o]);
        const float2 bq = unpack2_(acc23[o]);
        acc[o][0] = a.x; acc[o][1] = a.y; acc[o][2] = bq.x; acc[o][3] = bq.y;
    }

    const float inv_pi = 1.0f / PI_F;

    // Vectorized wi/wo loads: 4 px * 3 comps = 12 contiguous floats, 16B-aligned.
    float wiL[12], woL[12];
    {
        const float4* wip4 = reinterpret_cast<const float4*>(wi + gpix * 3);
        const float4* wop4 = reinterpret_cast<const float4*>(wo + gpix * 3);
#pragma unroll
        for (int q = 0; q < 3; ++q) {
            float4 a = __ldg(&wip4[q]);
            float4 bq = __ldg(&wop4[q]);
            wiL[q * 4 + 0] = a.x;  wiL[q * 4 + 1] = a.y;
            wiL[q * 4 + 2] = a.z;  wiL[q * 4 + 3] = a.w;
            woL[q * 4 + 0] = bq.x; woL[q * 4 + 1] = bq.y;
            woL[q * 4 + 2] = bq.z; woL[q * 4 + 3] = bq.w;
        }
    }

    float img[12];

#pragma unroll
    for (int j = 0; j < 4; ++j) {
        const long long g = gpix + j;

        // ---- activations ----
        float nx = tanh_(acc[0][j]);
        float ny = tanh_(acc[1][j]);
        float nz = tanh_(acc[2][j]);
        {
            const float inv = rsq_(fmaxf(nx * nx + ny * ny + nz * nz, 1e-24f));
            nx *= inv; ny *= inv; nz *= inv;
        }
        const float al0 = sigmoid_(acc[3][j]);
        const float al1 = sigmoid_(acc[4][j]);
        const float al2 = sigmoid_(acc[5][j]);
        float rough = sigmoid_(acc[6][j]);
        rough = fminf(fmaxf(rough, 0.001f), 1.0f);
        const float f0x = sigmoid_(acc[7][j]);
        const float f0y = sigmoid_(acc[8][j]);
        const float f0z = sigmoid_(acc[9][j]);

        // ---- light/view vectors ----
        float lx = wiL[j * 3 + 0], ly = wiL[j * 3 + 1], lz = wiL[j * 3 + 2];
        float vx = woL[j * 3 + 0], vy = woL[j * 3 + 1], vz = woL[j * 3 + 2];
        {
            const float il = rsq_(fmaxf(lx * lx + ly * ly + lz * lz, 1e-24f));
            lx *= il; ly *= il; lz *= il;
        }
        {
            const float iv = rsq_(fmaxf(vx * vx + vy * vy + vz * vz, 1e-24f));
            vx *= iv; vy *= iv; vz *= iv;
        }
        float hx = lx + vx, hy = ly + vy, hz = lz + vz;
        {
            const float ih = rsq_(fmaxf(hx * hx + hy * hy + hz * hz, 1e-24f));
            hx *= ih; hy *= ih; hz *= ih;
        }

        const float NdotH = fmaxf(nx * hx + ny * hy + nz * hz, 1e-8f);
        const float NdotL = fmaxf(nx * lx + ny * ly + nz * lz, 1e-8f);
        const float NdotV = fmaxf(nx * vx + ny * vy + nz * vz, 1e-8f);
        const float VdotH = fmaxf(vx * hx + vy * hy + vz * hz, 1e-8f);

        // ---- GGX ----
        const float alpha = rough * rough;
        const float a2    = alpha * alpha;
        const float den   = fmaf(NdotH * NdotH, a2 - 1.0f, 1.0f);
        const float D     = a2 * rcp_(PI_F * den * den);
        const float Fe    = ex2_(fmaf(-5.55473f, VdotH, -6.98316f) * VdotH);
        const float k     = alpha * 0.5f;
        const float G     = rcp_(fmaf(NdotL, 1.0f - k, k)) *
                            rcp_(fmaf(NdotV, 1.0f - k, k));
        const float DG    = 0.25f * D * G;

        const float F0 = fmaf(1.0f - f0x, Fe, f0x);
        const float F1 = fmaf(1.0f - f0y, Fe, f0y);
        const float F2 = fmaf(1.0f - f0z, Fe, f0z);

        img[j * 3 + 0] = fmaxf((al0 * (1.0f - f0x) * inv_pi + DG * F0) * NdotL, 0.0f);
        img[j * 3 + 1] = fmaxf((al1 * (1.0f - f0y) * inv_pi + DG * F1) * NdotL, 0.0f);
        img[j * 3 + 2] = fmaxf((al2 * (1.0f - f0z) * inv_pi + DG * F2) * NdotL, 0.0f);

        // ---- write data [B,H,W,12]: normal, albedo, rough x3, fresnel ----
        float4* dp = reinterpret_cast<float4*>(out_data + g * 12);
        dp[0] = make_float4(nx, ny, nz, al0);
        dp[1] = make_float4(al1, al2, rough, rough);
        dp[2] = make_float4(rough, f0x, f0y, f0z);
    }

    // ---- write imgs [B,H,W,3]: 12 contiguous floats, 16B-aligned ----
    {
        float4* ip = reinterpret_cast<float4*>(out_imgs + gpix * 3);
        ip[0] = make_float4(img[0], img[1], img[2],  img[3]);
        ip[1] = make_float4(img[4], img[5], img[6],  img[7]);
        ip[2] = make_float4(img[8], img[9], img[10], img[11]);
    }
}

extern "C" void kernel_launch(void* const* d_in, const int* in_sizes, int n_in,
                              void* d_out, int out_size)
{
    const float* feats     = (const float*)d_in[0];
    const float* wi        = (const float*)d_in[1];
    const float* wo        = (const float*)d_in[2];
    const float* w_normal  = (const float*)d_in[3];
    const float* w_albedo  = (const float*)d_in[4];
    const float* w_rough   = (const float*)d_in[5];
    const float* w_fresnel = (const float*)d_in[6];

    float* out = (float*)d_out;
    const long long NPIX = (long long)BATCH * HW;   // 524288
    float* out_imgs = out;                           // [B,H,W,3]
    float* out_data = out + NPIX * 3;                // [B,H,W,12]

    const int blocks = (int)(NPIX / PPB);            // 1024
    brdf_fused_kernel<<<blocks, NTHR>>>(feats, wi, wo,
                                        w_normal, w_albedo, w_rough, w_fresnel,
                                        out_imgs, out_data);
}

// round 4
// speedup vs baseline: 1.1737x; 1.1737x over previous
#include <cuda_runtime.h>
#include <cstdint>

#define PI_F 3.14159265358979323846f
#define LOG2E_F 1.44269504088896340736f

constexpr int C_IN   = 256;
constexpr int HW     = 256 * 256;      // 65536
constexpr int BATCH  = 8;
constexpr int PPT    = 4;              // pixels per thread (float4)
constexpr int NTHR   = 128;
constexpr int PPB    = NTHR * PPT;     // 512 pixels per block

constexpr int RING_CH  = 8;            // ring capacity in channels
constexpr int GROUP_CH = 2;            // channels per cp.async group
constexpr int NGROUPS  = C_IN / GROUP_CH;   // 128

// ---- fast math helpers (MUFU-based) ----
__device__ __forceinline__ float ex2_(float x) {
    float y; asm("ex2.approx.f32 %0, %1;" : "=f"(y) : "f"(x)); return y;
}
__device__ __forceinline__ float rcp_(float x) {
    float y; asm("rcp.approx.f32 %0, %1;" : "=f"(y) : "f"(x)); return y;
}
__device__ __forceinline__ float rsq_(float x) {
    float y; asm("rsqrt.approx.f32 %0, %1;" : "=f"(y) : "f"(x)); return y;
}
__device__ __forceinline__ float sigmoid_(float x) {
    return rcp_(1.0f + ex2_(-LOG2E_F * x));
}
__device__ __forceinline__ float tanh_(float x) {
    return 1.0f - 2.0f * rcp_(1.0f + ex2_(2.0f * LOG2E_F * x));
}

// ---- cp.async helpers ----
__device__ __forceinline__ void cpa16_(void* smem_dst, const void* gsrc) {
    unsigned s = (unsigned)__cvta_generic_to_shared(smem_dst);
    asm volatile("cp.async.cg.shared.global [%0], [%1], 16;\n"
                 :: "r"(s), "l"(gsrc) : "memory");
}
__device__ __forceinline__ void cpa_commit_() {
    asm volatile("cp.async.commit_group;\n" ::: "memory");
}
__device__ __forceinline__ void cpa_wait2_() {
    asm volatile("cp.async.wait_group 2;\n" ::: "memory");
}

__global__ __launch_bounds__(NTHR, 8)
void brdf_fused_kernel(const float* __restrict__ feats,
                       const float* __restrict__ wi,
                       const float* __restrict__ wo,
                       const float* __restrict__ w_normal,
                       const float* __restrict__ w_albedo,
                       const float* __restrict__ w_rough,
                       const float* __restrict__ w_fresnel,
                       float* __restrict__ out_imgs,
                       float* __restrict__ out_data)
{
    // Weights: per channel 12 floats (10 used + 2 pad) -> 2x LDS.128 + LDS.64.
    __shared__ float sw[C_IN * 12];
    // feats ring: 8 channels x 128 threads x float4 = 16 KB. Each thread only
    // touches its own [slot][tid] cell -> no intra-loop synchronization.
    __shared__ float4 ring[RING_CH][NTHR];

    const int tid = threadIdx.x;
    for (int i = tid; i < C_IN; i += NTHR) {
        float* p = &sw[i * 12];
        p[0]  = w_normal[0 * C_IN + i];
        p[1]  = w_normal[1 * C_IN + i];
        p[2]  = w_normal[2 * C_IN + i];
        p[3]  = w_albedo[0 * C_IN + i];
        p[4]  = w_albedo[1 * C_IN + i];
        p[5]  = w_albedo[2 * C_IN + i];
        p[6]  = w_rough[i];
        p[7]  = w_fresnel[0 * C_IN + i];
        p[8]  = w_fresnel[1 * C_IN + i];
        p[9]  = w_fresnel[2 * C_IN + i];
        p[10] = 0.f;
        p[11] = 0.f;
    }
    __syncthreads();

    const long long gpix = (long long)blockIdx.x * PPB + (long long)tid * PPT;
    const int b  = (int)(gpix / HW);
    const int hw = (int)(gpix % HW);

    // Byte pointer to this thread's float4 in channel 0 of batch b.
    const char* gp = reinterpret_cast<const char*>(
        feats + (size_t)b * C_IN * HW + hw);
    const size_t CH_BYTES = (size_t)HW * 4;   // 256 KB per channel plane

    float acc[10][4];
#pragma unroll
    for (int o = 0; o < 10; ++o)
#pragma unroll
        for (int j = 0; j < 4; ++j) acc[o][j] = 0.f;

    // ---- prologue: issue groups 0..2 (channels 0..5), 3 groups in flight ----
#pragma unroll
    for (int c0 = 0; c0 < 3 * GROUP_CH; c0 += GROUP_CH) {
        cpa16_(&ring[c0 & (RING_CH - 1)][tid],       gp + (size_t)c0 * CH_BYTES);
        cpa16_(&ring[(c0 + 1) & (RING_CH - 1)][tid], gp + (size_t)(c0 + 1) * CH_BYTES);
        cpa_commit_();
    }

    // ---- main loop: 128 groups of 2 channels ----
#pragma unroll 4
    for (int g = 0; g < NGROUPS; ++g) {
        cpa_wait2_();          // group g's data resident in smem
        const int c = g * GROUP_CH;

#pragma unroll
        for (int d = 0; d < GROUP_CH; ++d) {
            const int ch = c + d;
            const float4 f = ring[ch & (RING_CH - 1)][tid];
            const float* swp = &sw[ch * 12];
            const float4 wA = *reinterpret_cast<const float4*>(swp + 0);
            const float4 wB = *reinterpret_cast<const float4*>(swp + 4);
            const float2 wC = *reinterpret_cast<const float2*>(swp + 8);
            const float w[10] = {wA.x, wA.y, wA.z, wA.w, wB.x,
                                 wB.y, wB.z, wB.w, wC.x, wC.y};
            const float fv[4] = {f.x, f.y, f.z, f.w};
#pragma unroll
            for (int o = 0; o < 10; ++o)
#pragma unroll
                for (int j = 0; j < 4; ++j)
                    acc[o][j] = fmaf(fv[j], w[o], acc[o][j]);
        }

        // issue group g+3 (channels c+6, c+7); empty commit in the tail keeps
        // the wait_group bookkeeping uniform.
        const int cn = c + 3 * GROUP_CH;
        if (cn < C_IN) {
            cpa16_(&ring[cn & (RING_CH - 1)][tid],       gp + (size_t)cn * CH_BYTES);
            cpa16_(&ring[(cn + 1) & (RING_CH - 1)][tid], gp + (size_t)(cn + 1) * CH_BYTES);
        }
        cpa_commit_();
    }

    const float inv_pi = 1.0f / PI_F;

    // Vectorized wi/wo loads: 4 px * 3 comps = 12 contiguous floats, 16B-aligned.
    float wiL[12], woL[12];
    {
        const float4* wip4 = reinterpret_cast<const float4*>(wi + gpix * 3);
        const float4* wop4 = reinterpret_cast<const float4*>(wo + gpix * 3);
#pragma unroll
        for (int q = 0; q < 3; ++q) {
            float4 a  = __ldg(&wip4[q]);
            float4 bq = __ldg(&wop4[q]);
            wiL[q * 4 + 0] = a.x;  wiL[q * 4 + 1] = a.y;
            wiL[q * 4 + 2] = a.z;  wiL[q * 4 + 3] = a.w;
            woL[q * 4 + 0] = bq.x; woL[q * 4 + 1] = bq.y;
            woL[q * 4 + 2] = bq.z; woL[q * 4 + 3] = bq.w;
        }
    }

    float img[12];

#pragma unroll
    for (int j = 0; j < 4; ++j) {
        const long long g = gpix + j;

        // ---- activations ----
        float nx = tanh_(acc[0][j]);
        float ny = tanh_(acc[1][j]);
        float nz = tanh_(acc[2][j]);
        {
            const float inv = rsq_(fmaxf(nx * nx + ny * ny + nz * nz, 1e-24f));
            nx *= inv; ny *= inv; nz *= inv;
        }
        const float al0 = sigmoid_(acc[3][j]);
        const float al1 = sigmoid_(acc[4][j]);
        const float al2 = sigmoid_(acc[5][j]);
        float rough = sigmoid_(acc[6][j]);
        rough = fminf(fmaxf(rough, 0.001f), 1.0f);
        const float f0x = sigmoid_(acc[7][j]);
        const float f0y = sigmoid_(acc[8][j]);
        const float f0z = sigmoid_(acc[9][j]);

        // ---- light/view vectors ----
        float lx = wiL[j * 3 + 0], ly = wiL[j * 3 + 1], lz = wiL[j * 3 + 2];
        float vx = woL[j * 3 + 0], vy = woL[j * 3 + 1], vz = woL[j * 3 + 2];
        {
            const float il = rsq_(fmaxf(lx * lx + ly * ly + lz * lz, 1e-24f));
            lx *= il; ly *= il; lz *= il;
        }
        {
            const float iv = rsq_(fmaxf(vx * vx + vy * vy + vz * vz, 1e-24f));
            vx *= iv; vy *= iv; vz *= iv;
        }
        float hx = lx + vx, hy = ly + vy, hz = lz + vz;
        {
            const float ih = rsq_(fmaxf(hx * hx + hy * hy + hz * hz, 1e-24f));
            hx *= ih; hy *= ih; hz *= ih;
        }

        const float NdotH = fmaxf(nx * hx + ny * hy + nz * hz, 1e-8f);
        const float NdotL = fmaxf(nx * lx + ny * ly + nz * lz, 1e-8f);
        const float NdotV = fmaxf(nx * vx + ny * vy + nz * vz, 1e-8f);
        const float VdotH = fmaxf(vx * hx + vy * hy + vz * hz, 1e-8f);

        // ---- GGX ----
        const float alpha = rough * rough;
        const float a2    = alpha * alpha;
        const float den   = fmaf(NdotH * NdotH, a2 - 1.0f, 1.0f);
        const float D     = a2 * rcp_(PI_F * den * den);
        const float Fe    = ex2_(fmaf(-5.55473f, VdotH, -6.98316f) * VdotH);
        const float k     = alpha * 0.5f;
        const float G     = rcp_(fmaf(NdotL, 1.0f - k, k)) *
                            rcp_(fmaf(NdotV, 1.0f - k, k));
        const float DG    = 0.25f * D * G;

        const float F0 = fmaf(1.0f - f0x, Fe, f0x);
        const float F1 = fmaf(1.0f - f0y, Fe, f0y);
        const float F2 = fmaf(1.0f - f0z, Fe, f0z);

        img[j * 3 + 0] = fmaxf((al0 * (1.0f - f0x) * inv_pi + DG * F0) * NdotL, 0.0f);
        img[j * 3 + 1] = fmaxf((al1 * (1.0f - f0y) * inv_pi + DG * F1) * NdotL, 0.0f);
        img[j * 3 + 2] = fmaxf((al2 * (1.0f - f0z) * inv_pi + DG * F2) * NdotL, 0.0f);

        // ---- write data [B,H,W,12]: normal, albedo, rough x3, fresnel ----
        float4* dp = reinterpret_cast<float4*>(out_data + g * 12);
        dp[0] = make_float4(nx, ny, nz, al0);
        dp[1] = make_float4(al1, al2, rough, rough);
        dp[2] = make_float4(rough, f0x, f0y, f0z);
    }

    // ---- write imgs [B,H,W,3]: 12 contiguous floats, 16B-aligned ----
    {
        float4* ip = reinterpret_cast<float4*>(out_imgs + gpix * 3);
        ip[0] = make_float4(img[0], img[1], img[2],  img[3]);
        ip[1] = make_float4(img[4], img[5], img[6],  img[7]);
        ip[2] = make_float4(img[8], img[9], img[10], img[11]);
    }
}

extern "C" void kernel_launch(void* const* d_in, const int* in_sizes, int n_in,
                              void* d_out, int out_size)
{
    const float* feats     = (const float*)d_in[0];
    const float* wi        = (const float*)d_in[1];
    const float* wo        = (const float*)d_in[2];
    const float* w_normal  = (const float*)d_in[3];
    const float* w_albedo  = (const float*)d_in[4];
    const float* w_rough   = (const float*)d_in[5];
    const float* w_fresnel = (const float*)d_in[6];

    float* out = (float*)d_out;
    const long long NPIX = (long long)BATCH * HW;   // 524288
    float* out_imgs = out;                           // [B,H,W,3]
    float* out_data = out + NPIX * 3;                // [B,H,W,12]

    const int blocks = (int)(NPIX / PPB);            // 1024
    brdf_fused_kernel<<<blocks, NTHR>>>(feats, wi, wo,
                                        w_normal, w_albedo, w_rough, w_fresnel,
                                        out_imgs, out_data);
}